// round 7
// baseline (speedup 1.0000x reference)
#include <cuda_runtime.h>
#include <cuda_bf16.h>
#include <math.h>

#define Bv 2
#define Sv 2048
#define Dv 1024
#define Hv 16
#define DHv 64
#define Mv (Bv*Sv)        // 4096
#define PAD 65

// Scratch (module-static device globals; no runtime allocation)
__device__ float g_q[(size_t)Bv*Hv*Sv*DHv];   // [b][h][s][dh]
__device__ float g_k[(size_t)Bv*Hv*Sv*DHv];
__device__ float g_v[(size_t)Bv*Hv*Sv*DHv];
__device__ float g_o[(size_t)Bv*Sv*Dv];       // [b][s][h*DH+dh]

// ---------------------------------------------------------------------------
// Kernel 1: fused QKV projection.  grid(Mv/64, H), block 256.
// One block computes Q, K and V 64x64 tiles for one head, sharing the
// x tile (loaded once instead of three times).  K-chunk = 32.
// ---------------------------------------------------------------------------
__global__ __launch_bounds__(256) void qkv_kernel(
    const float* __restrict__ x,
    const float* __restrict__ Wq, const float* __restrict__ bq,
    const float* __restrict__ Wk, const float* __restrict__ bk,
    const float* __restrict__ Wv, const float* __restrict__ bv)
{
    __shared__ float As[32][PAD];      // [k][m], padded transposed store
    __shared__ float Bs[3][32][64];    // [mtx][k][n]

    const int h   = blockIdx.y;
    const int r0  = blockIdx.x * 64;
    const int tid = threadIdx.x;
    const int tx  = tid & 15;
    const int ty  = tid >> 4;

    const float* Wm[3] = { Wq + (size_t)h * Dv * DHv,
                           Wk + (size_t)h * Dv * DHv,
                           Wv + (size_t)h * Dv * DHv };

    float acc[3][4][4] = {};

    for (int kk = 0; kk < Dv; kk += 32) {
        // A tile: 64 rows x 32 k (transposed store), 2 float4 per thread
        #pragma unroll
        for (int l = 0; l < 2; l++) {
            int fid = tid + l * 256;       // 0..511
            int m   = fid >> 3;            // 0..63
            int kq  = fid & 7;             // 0..7
            float4 v = *(const float4*)&x[(size_t)(r0 + m) * Dv + kk + kq * 4];
            As[kq*4+0][m] = v.x; As[kq*4+1][m] = v.y;
            As[kq*4+2][m] = v.z; As[kq*4+3][m] = v.w;
        }
        // B tiles: 3 matrices x (32 k x 64 n), 2 float4 per thread each
        #pragma unroll
        for (int mtx = 0; mtx < 3; mtx++) {
            #pragma unroll
            for (int l = 0; l < 2; l++) {
                int fid = tid + l * 256;
                int k   = fid >> 4;        // 0..31
                int nq  = fid & 15;
                *(float4*)&Bs[mtx][k][nq*4] =
                    *(const float4*)&Wm[mtx][(size_t)(kk + k) * DHv + nq * 4];
            }
        }
        __syncthreads();
        #pragma unroll
        for (int k = 0; k < 32; k++) {
            float av[4];
            #pragma unroll
            for (int i = 0; i < 4; i++) av[i] = As[k][ty*4+i];
            #pragma unroll
            for (int mtx = 0; mtx < 3; mtx++) {
                float4 b = *(float4*)&Bs[mtx][k][tx*4];
                float bw[4] = {b.x, b.y, b.z, b.w};
                #pragma unroll
                for (int i = 0; i < 4; i++)
                    #pragma unroll
                    for (int j = 0; j < 4; j++)
                        acc[mtx][i][j] += av[i] * bw[j];
            }
        }
        __syncthreads();
    }

    const float* biasm[3] = { bq, bk, bv };
    float* outm[3] = { g_q, g_k, g_v };
    #pragma unroll
    for (int mtx = 0; mtx < 3; mtx++) {
        #pragma unroll
        for (int i = 0; i < 4; i++) {
            int r = r0 + ty*4 + i;
            int b_idx = r / Sv;
            int s     = r % Sv;
            float* dst = outm[mtx] + ((size_t)(b_idx * Hv + h) * Sv + s) * DHv;
            #pragma unroll
            for (int j = 0; j < 4; j++) {
                int c = tx*4 + j;
                dst[c] = acc[mtx][i][j] + biasm[mtx][h * DHv + c];
            }
        }
    }
}

// ---------------------------------------------------------------------------
// Kernel 2: flash attention.  grid(B*H, S/64), block 256 (16x16).
// 64 query rows x 64 kv cols per tile, DH=64.
// - 1/sqrt(DH) folded into the Q smem store (exact: scale is a power of 2)
// - online softmax in registers (width-16 shfl reductions)
// - 2-stage K/V pipeline: prefetch next tile into registers during compute,
//   store to alternate smem buffer after PV, one barrier per iteration.
// Smem: Qs | Ks0 Vs0 | Ks1 Vs1 | Ps   (6 * 64*PAD floats ~ 100 KB)
// ---------------------------------------------------------------------------
__global__ __launch_bounds__(256) void attn_kernel()
{
    extern __shared__ float sm[];
    float* Qs = sm;                       // [64][PAD]
    float* Ps = sm + 5 * 64 * PAD;        // [64][PAD]

    const int bh  = blockIdx.x;                 // b*H + h
    const int s0  = blockIdx.y * 64;
    const int tid = threadIdx.x;
    const int tx  = tid & 15;
    const int ty  = tid >> 4;

    const float* qbase = g_q + (size_t)bh * Sv * DHv;
    const float* kbase = g_k + (size_t)bh * Sv * DHv;
    const float* vbase = g_v + (size_t)bh * Sv * DHv;

    // Per-thread load coordinates (4 fragments of 256 threads cover 64x64)
    const int lrow = tid >> 4;     // 0..15, +16 per fragment
    const int ldq  = tid & 15;     // float4 column

    // Load Q tile (row-major, padded), pre-scaled by 1/sqrt(DH)
    const float qscale = 0.125f;
    #pragma unroll
    for (int l = 0; l < 4; l++) {
        int row = lrow + l * 16;
        float4 v = *(const float4*)&qbase[(size_t)(s0 + row) * DHv + ldq * 4];
        Qs[row*PAD + ldq*4+0] = v.x * qscale;
        Qs[row*PAD + ldq*4+1] = v.y * qscale;
        Qs[row*PAD + ldq*4+2] = v.z * qscale;
        Qs[row*PAD + ldq*4+3] = v.w * qscale;
    }

    // Prefetch tile 0 into registers, then store to buffer 0
    float4 rk[4], rv[4];
    #pragma unroll
    for (int l = 0; l < 4; l++) {
        int row = lrow + l * 16;
        rk[l] = *(const float4*)&kbase[(size_t)row * DHv + ldq * 4];
        rv[l] = *(const float4*)&vbase[(size_t)row * DHv + ldq * 4];
    }
    {
        float* Kd = sm + 1 * 64 * PAD;
        float* Vd = sm + 2 * 64 * PAD;
        #pragma unroll
        for (int l = 0; l < 4; l++) {
            int row = lrow + l * 16;
            Kd[row*PAD + ldq*4+0] = rk[l].x; Kd[row*PAD + ldq*4+1] = rk[l].y;
            Kd[row*PAD + ldq*4+2] = rk[l].z; Kd[row*PAD + ldq*4+3] = rk[l].w;
            Vd[row*PAD + ldq*4+0] = rv[l].x; Vd[row*PAD + ldq*4+1] = rv[l].y;
            Vd[row*PAD + ldq*4+2] = rv[l].z; Vd[row*PAD + ldq*4+3] = rv[l].w;
        }
    }

    float o[4][4] = {};
    float m_run[4], l_run[4];
    #pragma unroll
    for (int i = 0; i < 4; i++) { m_run[i] = -INFINITY; l_run[i] = 0.f; }

    __syncthreads();

    int it = 0;
    for (int t0 = 0; t0 < Sv; t0 += 64, it ^= 1) {
        const bool has_next = (t0 + 64) < Sv;

        // Prefetch next tile into registers (latency hidden by compute below)
        if (has_next) {
            #pragma unroll
            for (int l = 0; l < 4; l++) {
                int row = t0 + 64 + lrow + l * 16;
                rk[l] = *(const float4*)&kbase[(size_t)row * DHv + ldq * 4];
                rv[l] = *(const float4*)&vbase[(size_t)row * DHv + ldq * 4];
            }
        }

        const float* Ks = sm + (1 + 2*it) * 64 * PAD;
        const float* Vs = Ks + 64 * PAD;

        // Scores: S = (Q*scale) @ K^T  (4x4 per thread)
        float s[4][4] = {};
        #pragma unroll 8
        for (int dd = 0; dd < 64; dd++) {
            float av[4], bw[4];
            #pragma unroll
            for (int i = 0; i < 4; i++) av[i] = Qs[(ty*4+i)*PAD + dd];
            #pragma unroll
            for (int j = 0; j < 4; j++) bw[j] = Ks[(tx*4+j)*PAD + dd];
            #pragma unroll
            for (int i = 0; i < 4; i++)
                #pragma unroll
                for (int j = 0; j < 4; j++)
                    s[i][j] += av[i] * bw[j];
        }

        // Register online softmax; exp'd P to smem for PV GEMM.
        #pragma unroll
        for (int i = 0; i < 4; i++) {
            float mt = fmaxf(fmaxf(s[i][0], s[i][1]), fmaxf(s[i][2], s[i][3]));
            #pragma unroll
            for (int d = 1; d < 16; d <<= 1)
                mt = fmaxf(mt, __shfl_xor_sync(0xffffffffu, mt, d, 16));
            float mnew = fmaxf(m_run[i], mt);
            float corr = __expf(m_run[i] - mnew);
            float sum = 0.f;
            #pragma unroll
            for (int j = 0; j < 4; j++) {
                float p = __expf(s[i][j] - mnew);
                Ps[(ty*4+i)*PAD + tx*4+j] = p;
                sum += p;
            }
            #pragma unroll
            for (int d = 1; d < 16; d <<= 1)
                sum += __shfl_xor_sync(0xffffffffu, sum, d, 16);
            l_run[i] = l_run[i] * corr + sum;
            m_run[i] = mnew;
            #pragma unroll
            for (int j = 0; j < 4; j++) o[i][j] *= corr;
        }
        __syncthreads();   // Ps visible to all tx groups

        // O += P @ V
        #pragma unroll 8
        for (int jj = 0; jj < 64; jj++) {
            float pv[4], vv[4];
            #pragma unroll
            for (int i = 0; i < 4; i++) pv[i] = Ps[(ty*4+i)*PAD + jj];
            #pragma unroll
            for (int j = 0; j < 4; j++) vv[j] = Vs[jj*PAD + tx*4+j];
            #pragma unroll
            for (int i = 0; i < 4; i++)
                #pragma unroll
                for (int j = 0; j < 4; j++)
                    o[i][j] += pv[i] * vv[j];
        }

        // Drain prefetch into the alternate buffer (disjoint from buf 'it')
        if (has_next) {
            float* Kd = sm + (1 + 2*(it^1)) * 64 * PAD;
            float* Vd = Kd + 64 * PAD;
            #pragma unroll
            for (int l = 0; l < 4; l++) {
                int row = lrow + l * 16;
                Kd[row*PAD + ldq*4+0] = rk[l].x; Kd[row*PAD + ldq*4+1] = rk[l].y;
                Kd[row*PAD + ldq*4+2] = rk[l].z; Kd[row*PAD + ldq*4+3] = rk[l].w;
                Vd[row*PAD + ldq*4+0] = rv[l].x; Vd[row*PAD + ldq*4+1] = rv[l].y;
                Vd[row*PAD + ldq*4+2] = rv[l].z; Vd[row*PAD + ldq*4+3] = rv[l].w;
            }
        }
        __syncthreads();   // next-tile buffer ready; Ps/o reads complete
    }

    // Epilogue: normalize and write to concat layout [b][s][h*DH+dh]
    const int b_idx = bh / Hv;
    const int h     = bh % Hv;
    #pragma unroll
    for (int i = 0; i < 4; i++) {
        int r = ty*4 + i;
        float inv = 1.f / l_run[i];
        float4 w;
        w.x = o[i][0]*inv; w.y = o[i][1]*inv;
        w.z = o[i][2]*inv; w.w = o[i][3]*inv;
        float* dst = g_o + ((size_t)b_idx * Sv + (s0 + r)) * Dv + h * DHv + tx*4;
        *(float4*)dst = w;
    }
}

// ---------------------------------------------------------------------------
// Kernel 3: output projection. grid(Mv/64, Dv/64), block 256.
// out[64x64] = g_o_tile[64xK] @ Wo[Kx64] + bo.  K-chunk = 32.
// ---------------------------------------------------------------------------
__global__ __launch_bounds__(256) void proj_kernel(
    const float* __restrict__ Wo, const float* __restrict__ bo,
    float* __restrict__ out)
{
    __shared__ float As[32][PAD];
    __shared__ float Bs[32][64];

    const int r0  = blockIdx.x * 64;
    const int n0  = blockIdx.y * 64;
    const int tid = threadIdx.x;
    const int tx  = tid & 15;
    const int ty  = tid >> 4;

    float acc[4][4] = {};

    for (int kk = 0; kk < Dv; kk += 32) {
        #pragma unroll
        for (int l = 0; l < 2; l++) {
            int fid = tid + l * 256;
            int m   = fid >> 3;
            int kq  = fid & 7;
            float4 v = *(const float4*)&g_o[(size_t)(r0 + m) * Dv + kk + kq * 4];
            As[kq*4+0][m] = v.x; As[kq*4+1][m] = v.y;
            As[kq*4+2][m] = v.z; As[kq*4+3][m] = v.w;
        }
        #pragma unroll
        for (int l = 0; l < 2; l++) {
            int fid = tid + l * 256;
            int k   = fid >> 4;
            int nq  = fid & 15;
            *(float4*)&Bs[k][nq*4] =
                *(const float4*)&Wo[(size_t)(kk + k) * Dv + n0 + nq * 4];
        }
        __syncthreads();
        #pragma unroll
        for (int k = 0; k < 32; k++) {
            float av[4];
            #pragma unroll
            for (int i = 0; i < 4; i++) av[i] = As[k][ty*4+i];
            float4 b = *(float4*)&Bs[k][tx*4];
            float bw[4] = {b.x, b.y, b.z, b.w};
            #pragma unroll
            for (int i = 0; i < 4; i++)
                #pragma unroll
                for (int j = 0; j < 4; j++)
                    acc[i][j] += av[i] * bw[j];
        }
        __syncthreads();
    }

    #pragma unroll
    for (int i = 0; i < 4; i++) {
        int r = r0 + ty*4 + i;
        float* dst = out + (size_t)r * Dv + n0 + tx*4;
        float4 w;
        w.x = acc[i][0] + bo[n0 + tx*4 + 0];
        w.y = acc[i][1] + bo[n0 + tx*4 + 1];
        w.z = acc[i][2] + bo[n0 + tx*4 + 2];
        w.w = acc[i][3] + bo[n0 + tx*4 + 3];
        *(float4*)dst = w;
    }
}

// ---------------------------------------------------------------------------
extern "C" void kernel_launch(void* const* d_in, const int* in_sizes, int n_in,
                              void* d_out, int out_size)
{
    const float* x  = (const float*)d_in[0];
    const float* Wq = (const float*)d_in[1];
    const float* bq = (const float*)d_in[2];
    const float* Wk = (const float*)d_in[3];
    const float* bk = (const float*)d_in[4];
    const float* Wv = (const float*)d_in[5];
    const float* bv = (const float*)d_in[6];
    const float* Wo = (const float*)d_in[7];
    const float* bo = (const float*)d_in[8];
    float* out = (float*)d_out;

    qkv_kernel<<<dim3(Mv/64, Hv), 256>>>(x, Wq, bq, Wk, bk, Wv, bv);

    size_t smem = (size_t)(6 * 64 * PAD) * sizeof(float);
    cudaFuncSetAttribute(attn_kernel,
                         cudaFuncAttributeMaxDynamicSharedMemorySize, (int)smem);
    attn_kernel<<<dim3(Bv*Hv, Sv/64), 256, smem>>>();

    proj_kernel<<<dim3(Mv/64, Dv/64), 256>>>(Wo, bo, out);
}

// round 11
// speedup vs baseline: 1.6997x; 1.6997x over previous
#include <cuda_runtime.h>
#include <cuda_bf16.h>
#include <cstdint>
#include <math.h>

#define Bv 2
#define Sv 2048
#define Dv 1024
#define Hv 16
#define DHv 64
#define Mv (Bv*Sv)        // 4096
#define PAD 65
#define PADK 36
#define PADQ 68

// Scratch (module-static device globals; no runtime allocation)
__device__ float g_q[(size_t)Bv*Hv*Sv*DHv];   // [b][h][s][dh]
__device__ float g_k[(size_t)Bv*Hv*Sv*DHv];
__device__ float g_v[(size_t)Bv*Hv*Sv*DHv];
__device__ float g_o[(size_t)Bv*Sv*Dv];       // [b][s][h*DH+dh]
__device__ float g_wt[(size_t)3*Hv*DHv*Dv];   // W^T per matrix/head: [mtx][h][n][k]
__device__ float g_wot[(size_t)Dv*Dv];        // Wo^T: [n][k]

// ---------------------------------------------------------------------------
// tf32 helpers (mma.sync path — tcgen05 unavailable on this build target)
// ---------------------------------------------------------------------------
__device__ __forceinline__ uint32_t f2tf(float x) {
    uint32_t r;
    asm("cvt.rna.tf32.f32 %0, %1;" : "=r"(r) : "f"(x));
    return r;
}

__device__ __forceinline__ void mma_tf32(float* c, const uint32_t* a, const uint32_t* b) {
    asm volatile(
        "mma.sync.aligned.m16n8k8.row.col.f32.tf32.tf32.f32 "
        "{%0,%1,%2,%3}, {%4,%5,%6,%7}, {%8,%9}, {%0,%1,%2,%3};"
        : "+f"(c[0]), "+f"(c[1]), "+f"(c[2]), "+f"(c[3])
        : "r"(a[0]), "r"(a[1]), "r"(a[2]), "r"(a[3]), "r"(b[0]), "r"(b[1]));
}

// ---------------------------------------------------------------------------
// Weight transpose: dst[b][c][r] = src[b][r][c].  block (32,8), grid (R/32,C/32,batch)
// which: 0..2 -> g_wt + which*H*DH*D, 3 -> g_wot
// ---------------------------------------------------------------------------
__global__ __launch_bounds__(256) void transpose_kernel(
    const float* __restrict__ src, int R, int C, int which)
{
    __shared__ float t[32][33];
    float* dstbase = (which < 3) ? (g_wt + (size_t)which * Hv * DHv * Dv) : g_wot;

    const int b  = blockIdx.z;
    const float* s = src + (size_t)b * R * C;
    float* d       = dstbase + (size_t)b * R * C;
    const int r0 = blockIdx.x * 32, c0 = blockIdx.y * 32;
    const int tx = threadIdx.x, ty = threadIdx.y;

    #pragma unroll
    for (int i = 0; i < 4; i++)
        t[ty + 8*i][tx] = s[(size_t)(r0 + ty + 8*i) * C + c0 + tx];
    __syncthreads();
    #pragma unroll
    for (int i = 0; i < 4; i++)
        d[(size_t)(c0 + ty + 8*i) * R + r0 + tx] = t[tx][ty + 8*i];
}

// ---------------------------------------------------------------------------
// mma.sync tf32 GEMM core: acc[128x64] += A[128xDv] @ B[64xDv]^T.
// 256 threads = 8 warps in 4(M) x 2(N); warp tile 32x32 = 2x4 m16n8k8 frags.
// ---------------------------------------------------------------------------
__device__ __forceinline__ void gemm_mma_128x64(
    const float* __restrict__ Arows, const float* __restrict__ Brows,
    float acc[2][4][4], float* As /*[128*PADK]*/, float* Bs /*[64*PADK]*/)
{
    const int tid  = threadIdx.x;
    const int wid  = tid >> 5;
    const int lane = tid & 31;
    const int g    = lane >> 2;
    const int t    = lane & 3;
    const int wm   = (wid & 3) * 32;
    const int wn   = (wid >> 2) * 32;

    for (int kc = 0; kc < Dv; kc += 32) {
        #pragma unroll
        for (int l = 0; l < 4; l++) {
            int fid = tid + l * 256;
            int m   = fid >> 3;
            int kq  = fid & 7;
            float4 v = *(const float4*)&Arows[(size_t)m * Dv + kc + kq * 4];
            uint4 u;
            u.x = f2tf(v.x); u.y = f2tf(v.y); u.z = f2tf(v.z); u.w = f2tf(v.w);
            *(uint4*)&As[m * PADK + kq * 4] = u;
        }
        #pragma unroll
        for (int l = 0; l < 2; l++) {
            int fid = tid + l * 256;
            int n   = fid >> 3;
            int kq  = fid & 7;
            float4 v = *(const float4*)&Brows[(size_t)n * Dv + kc + kq * 4];
            uint4 u;
            u.x = f2tf(v.x); u.y = f2tf(v.y); u.z = f2tf(v.z); u.w = f2tf(v.w);
            *(uint4*)&Bs[n * PADK + kq * 4] = u;
        }
        __syncthreads();

        #pragma unroll
        for (int ks = 0; ks < 32; ks += 8) {
            uint32_t a[2][4], b[4][2];
            #pragma unroll
            for (int mi = 0; mi < 2; mi++) {
                int r0 = wm + mi * 16 + g;
                a[mi][0] = __float_as_uint(As[r0 * PADK + ks + t]);
                a[mi][1] = __float_as_uint(As[(r0 + 8) * PADK + ks + t]);
                a[mi][2] = __float_as_uint(As[r0 * PADK + ks + t + 4]);
                a[mi][3] = __float_as_uint(As[(r0 + 8) * PADK + ks + t + 4]);
            }
            #pragma unroll
            for (int ni = 0; ni < 4; ni++) {
                int nr = wn + ni * 8 + g;
                b[ni][0] = __float_as_uint(Bs[nr * PADK + ks + t]);
                b[ni][1] = __float_as_uint(Bs[nr * PADK + ks + t + 4]);
            }
            #pragma unroll
            for (int mi = 0; mi < 2; mi++)
                #pragma unroll
                for (int ni = 0; ni < 4; ni++)
                    mma_tf32(acc[mi][ni], a[mi], b[ni]);
        }
        __syncthreads();
    }
}

// ---------------------------------------------------------------------------
// Kernel 1: QKV projection via mma.sync tf32.  grid(Mv/128, H, 3), block 256.
// ---------------------------------------------------------------------------
__global__ __launch_bounds__(256) void qkv_mma_kernel(
    const float* __restrict__ x,
    const float* __restrict__ bq,
    const float* __restrict__ bk,
    const float* __restrict__ bv)
{
    __shared__ float As[128 * PADK];
    __shared__ float Bs[64 * PADK];

    const int h   = blockIdx.y;
    const int mtx = blockIdx.z;
    const int r0  = blockIdx.x * 128;

    const float* Brows = g_wt + ((size_t)(mtx * Hv + h) * DHv) * Dv;
    const float* bias  = ((mtx == 0) ? bq : (mtx == 1) ? bk : bv) + h * DHv;
    float* out         = (mtx == 0) ? g_q : (mtx == 1) ? g_k : g_v;

    float acc[2][4][4] = {};
    gemm_mma_128x64(x + (size_t)r0 * Dv, Brows, acc, As, Bs);

    const int lane = threadIdx.x & 31;
    const int wid  = threadIdx.x >> 5;
    const int g    = lane >> 2;
    const int t    = lane & 3;
    const int wm   = (wid & 3) * 32;
    const int wn   = (wid >> 2) * 32;

    #pragma unroll
    for (int mi = 0; mi < 2; mi++) {
        #pragma unroll
        for (int ni = 0; ni < 4; ni++) {
            int col = wn + ni * 8 + 2 * t;
            #pragma unroll
            for (int half = 0; half < 2; half++) {
                int m = r0 + wm + mi * 16 + g + half * 8;
                int b = m >> 11;               // / Sv
                int s = m & (Sv - 1);
                float* dst = out + ((size_t)(b * Hv + h) * Sv + s) * DHv + col;
                float2 w;
                w.x = acc[mi][ni][2*half + 0] + bias[col + 0];
                w.y = acc[mi][ni][2*half + 1] + bias[col + 1];
                *(float2*)dst = w;
            }
        }
    }
}

// ---------------------------------------------------------------------------
// Kernel 3: output projection via mma.sync tf32.  grid(Mv/128, Dv/64), block 256.
// ---------------------------------------------------------------------------
__global__ __launch_bounds__(256) void proj_mma_kernel(
    const float* __restrict__ bo, float* __restrict__ out)
{
    __shared__ float As[128 * PADK];
    __shared__ float Bs[64 * PADK];

    const int r0 = blockIdx.x * 128;
    const int n0 = blockIdx.y * 64;

    float acc[2][4][4] = {};
    gemm_mma_128x64(g_o + (size_t)r0 * Dv, g_wot + (size_t)n0 * Dv, acc, As, Bs);

    const int lane = threadIdx.x & 31;
    const int wid  = threadIdx.x >> 5;
    const int g    = lane >> 2;
    const int t    = lane & 3;
    const int wm   = (wid & 3) * 32;
    const int wn   = (wid >> 2) * 32;

    #pragma unroll
    for (int mi = 0; mi < 2; mi++) {
        #pragma unroll
        for (int ni = 0; ni < 4; ni++) {
            int col = n0 + wn + ni * 8 + 2 * t;
            #pragma unroll
            for (int half = 0; half < 2; half++) {
                int m = r0 + wm + mi * 16 + g + half * 8;
                float* dst = out + (size_t)m * Dv + col;
                float2 w;
                w.x = acc[mi][ni][2*half + 0] + bo[col + 0];
                w.y = acc[mi][ni][2*half + 1] + bo[col + 1];
                *(float2*)dst = w;
            }
        }
    }
}

// ---------------------------------------------------------------------------
// Kernel 2: flash attention.  grid(B*H, S/64), block 256 (8 warps).
// S = QK^T via mma.sync tf32 on warps 0-3 (warp-tile m16 x n64 -> each warp
// owns whole score rows); online softmax on accumulator fragments with
// width-4 shuffles; exp'd P -> Ps smem; PV stays the verified fp32 loop
// on all 8 warps.  K tiles stored tf32 (stride PADQ), V fp32 (stride PAD).
// Smem floats:
//   Qs 0           [64*PADQ]   tf32, pre-scaled by 1/8
//   Ks0 4352 / Ks1 8704        tf32 [64*PADQ] double buffer
//   Vs0 13056 / Vs1 17216      fp32 [64*PAD] double buffer
//   Ps 21376       [64*PAD]
//   crow 25536[64], lrow 25600[64]          total 25664 f = 102656 B
// ---------------------------------------------------------------------------
__global__ __launch_bounds__(256) void attn_kernel()
{
    extern __shared__ float sm[];
    float* Qs   = sm;
    float* Ps   = sm + 21376;
    float* crow = sm + 25536;
    float* lrow = sm + 25600;

    const int bh  = blockIdx.x;                 // b*H + h
    const int s0  = blockIdx.y * 64;
    const int tid = threadIdx.x;
    const int tx  = tid & 15;
    const int ty  = tid >> 4;
    const int wid = tid >> 5;
    const int lane = tid & 31;
    const int g   = lane >> 2;
    const int t   = lane & 3;
    const int wm  = (wid & 3) * 16;             // S-mma row block (warps 0-3)

    const float* qbase = g_q + (size_t)bh * Sv * DHv;
    const float* kbase = g_k + (size_t)bh * Sv * DHv;
    const float* vbase = g_v + (size_t)bh * Sv * DHv;

    const int lrw = tid >> 4;      // 0..15 (+16 per fragment)
    const int ldq = tid & 15;      // float4 column

    // Q tile: tf32, pre-scaled by 1/sqrt(DH)=0.125 (exact power of 2)
    #pragma unroll
    for (int l = 0; l < 4; l++) {
        int row = lrw + l * 16;
        float4 v = *(const float4*)&qbase[(size_t)(s0 + row) * DHv + ldq * 4];
        Qs[row*PADQ + ldq*4+0] = __uint_as_float(f2tf(v.x * 0.125f));
        Qs[row*PADQ + ldq*4+1] = __uint_as_float(f2tf(v.y * 0.125f));
        Qs[row*PADQ + ldq*4+2] = __uint_as_float(f2tf(v.z * 0.125f));
        Qs[row*PADQ + ldq*4+3] = __uint_as_float(f2tf(v.w * 0.125f));
    }

    // Prefetch tile 0 into registers, then store (K as tf32, V raw)
    float4 rk[4], rv[4];
    #pragma unroll
    for (int l = 0; l < 4; l++) {
        int row = lrw + l * 16;
        rk[l] = *(const float4*)&kbase[(size_t)row * DHv + ldq * 4];
        rv[l] = *(const float4*)&vbase[(size_t)row * DHv + ldq * 4];
    }
    {
        float* Kd = sm + 4352;
        float* Vd = sm + 13056;
        #pragma unroll
        for (int l = 0; l < 4; l++) {
            int row = lrw + l * 16;
            Kd[row*PADQ + ldq*4+0] = __uint_as_float(f2tf(rk[l].x));
            Kd[row*PADQ + ldq*4+1] = __uint_as_float(f2tf(rk[l].y));
            Kd[row*PADQ + ldq*4+2] = __uint_as_float(f2tf(rk[l].z));
            Kd[row*PADQ + ldq*4+3] = __uint_as_float(f2tf(rk[l].w));
            Vd[row*PAD + ldq*4+0] = rv[l].x; Vd[row*PAD + ldq*4+1] = rv[l].y;
            Vd[row*PAD + ldq*4+2] = rv[l].z; Vd[row*PAD + ldq*4+3] = rv[l].w;
        }
    }

    float o[4][4] = {};
    float m_run[2] = { -INFINITY, -INFINITY };   // rows wm+g, wm+g+8 (warps 0-3)
    float l_run[2] = { 0.f, 0.f };

    __syncthreads();

    int it = 0;
    for (int t0 = 0; t0 < Sv; t0 += 64, it ^= 1) {
        const bool has_next = (t0 + 64) < Sv;

        if (has_next) {
            #pragma unroll
            for (int l = 0; l < 4; l++) {
                int row = t0 + 64 + lrw + l * 16;
                rk[l] = *(const float4*)&kbase[(size_t)row * DHv + ldq * 4];
                rv[l] = *(const float4*)&vbase[(size_t)row * DHv + ldq * 4];
            }
        }

        const float* Ks = sm + 4352 + it * 4352;
        const float* Vs = sm + 13056 + it * 4160;

        if (wid < 4) {
            // S = Q @ K^T : warp-tile m16 x n64, 8 k-steps
            float sacc[8][4] = {};
            #pragma unroll
            for (int ks = 0; ks < 64; ks += 8) {
                uint32_t a[4];
                a[0] = __float_as_uint(Qs[(wm + g) * PADQ + ks + t]);
                a[1] = __float_as_uint(Qs[(wm + g + 8) * PADQ + ks + t]);
                a[2] = __float_as_uint(Qs[(wm + g) * PADQ + ks + t + 4]);
                a[3] = __float_as_uint(Qs[(wm + g + 8) * PADQ + ks + t + 4]);
                #pragma unroll
                for (int ni = 0; ni < 8; ni++) {
                    uint32_t b[2];
                    b[0] = __float_as_uint(Ks[(ni * 8 + g) * PADQ + ks + t]);
                    b[1] = __float_as_uint(Ks[(ni * 8 + g) * PADQ + ks + t + 4]);
                    mma_tf32(sacc[ni], a, b);
                }
            }

            // Online softmax on fragments.  Row wm+g+8*half is held by
            // lanes 4g..4g+3 (t=0..3) -> width-4 xor shuffles.
            #pragma unroll
            for (int half = 0; half < 2; half++) {
                const int r = wm + g + half * 8;
                float mloc = -INFINITY;
                #pragma unroll
                for (int ni = 0; ni < 8; ni++)
                    mloc = fmaxf(mloc, fmaxf(sacc[ni][2*half], sacc[ni][2*half+1]));
                mloc = fmaxf(mloc, __shfl_xor_sync(0xffffffffu, mloc, 1, 4));
                mloc = fmaxf(mloc, __shfl_xor_sync(0xffffffffu, mloc, 2, 4));
                float mnew = fmaxf(m_run[half], mloc);
                float corr = __expf(m_run[half] - mnew);
                float sum = 0.f;
                #pragma unroll
                for (int ni = 0; ni < 8; ni++) {
                    float p0 = __expf(sacc[ni][2*half]   - mnew);
                    float p1 = __expf(sacc[ni][2*half+1] - mnew);
                    Ps[r * PAD + ni * 8 + 2 * t]     = p0;
                    Ps[r * PAD + ni * 8 + 2 * t + 1] = p1;
                    sum += p0 + p1;
                }
                sum += __shfl_xor_sync(0xffffffffu, sum, 1, 4);
                sum += __shfl_xor_sync(0xffffffffu, sum, 2, 4);
                l_run[half] = l_run[half] * corr + sum;
                m_run[half] = mnew;
                if (t == 0) crow[r] = corr;
            }
        }
        __syncthreads();   // A: Ps + crow visible

        // Rescale accumulators, then O += P @ V (fp32, all 8 warps)
        float cr[4];
        #pragma unroll
        for (int i = 0; i < 4; i++) cr[i] = crow[ty*4 + i];
        #pragma unroll
        for (int i = 0; i < 4; i++)
            #pragma unroll
            for (int j = 0; j < 4; j++)
                o[i][j] *= cr[i];

        #pragma unroll 8
        for (int jj = 0; jj < 64; jj++) {
            float pv[4], vv[4];
            #pragma unroll
            for (int i = 0; i < 4; i++) pv[i] = Ps[(ty*4+i)*PAD + jj];
            #pragma unroll
            for (int j = 0; j < 4; j++) vv[j] = Vs[jj*PAD + tx*4+j];
            #pragma unroll
            for (int i = 0; i < 4; i++)
                #pragma unroll
                for (int j = 0; j < 4; j++)
                    o[i][j] += pv[i] * vv[j];
        }

        // Drain prefetch into alternate buffers (disjoint from buf 'it')
        if (has_next) {
            float* Kd = sm + 4352 + (it ^ 1) * 4352;
            float* Vd = sm + 13056 + (it ^ 1) * 4160;
            #pragma unroll
            for (int l = 0; l < 4; l++) {
                int row = lrw + l * 16;
                Kd[row*PADQ + ldq*4+0] = __uint_as_float(f2tf(rk[l].x));
                Kd[row*PADQ + ldq*4+1] = __uint_as_float(f2tf(rk[l].y));
                Kd[row*PADQ + ldq*4+2] = __uint_as_float(f2tf(rk[l].z));
                Kd[row*PADQ + ldq*4+3] = __uint_as_float(f2tf(rk[l].w));
                Vd[row*PAD + ldq*4+0] = rv[l].x; Vd[row*PAD + ldq*4+1] = rv[l].y;
                Vd[row*PAD + ldq*4+2] = rv[l].z; Vd[row*PAD + ldq*4+3] = rv[l].w;
            }
        }
        __syncthreads();   // B: buffers ready; Ps/crow reads complete
    }

    // Publish row sums, then normalize + write concat layout
    if (wid < 4 && t == 0) {
        lrow[wm + g]     = l_run[0];
        lrow[wm + g + 8] = l_run[1];
    }
    __syncthreads();

    const int b_idx = bh / Hv;
    const int h     = bh % Hv;
    #pragma unroll
    for (int i = 0; i < 4; i++) {
        int r = ty*4 + i;
        float inv = 1.f / lrow[r];
        float4 w;
        w.x = o[i][0]*inv; w.y = o[i][1]*inv;
        w.z = o[i][2]*inv; w.w = o[i][3]*inv;
        float* dst = g_o + ((size_t)b_idx * Sv + (s0 + r)) * Dv + h * DHv + tx*4;
        *(float4*)dst = w;
    }
}

// ---------------------------------------------------------------------------
extern "C" void kernel_launch(void* const* d_in, const int* in_sizes, int n_in,
                              void* d_out, int out_size)
{
    const float* x  = (const float*)d_in[0];
    const float* Wq = (const float*)d_in[1];
    const float* bq = (const float*)d_in[2];
    const float* Wk = (const float*)d_in[3];
    const float* bk = (const float*)d_in[4];
    const float* Wv = (const float*)d_in[5];
    const float* bv = (const float*)d_in[6];
    const float* Wo = (const float*)d_in[7];
    const float* bo = (const float*)d_in[8];
    float* out = (float*)d_out;

    // Pre-transpose weights into [n][k] layout for mma B operands
    transpose_kernel<<<dim3(Dv/32, DHv/32, Hv), dim3(32, 8)>>>(Wq, Dv, DHv, 0);
    transpose_kernel<<<dim3(Dv/32, DHv/32, Hv), dim3(32, 8)>>>(Wk, Dv, DHv, 1);
    transpose_kernel<<<dim3(Dv/32, DHv/32, Hv), dim3(32, 8)>>>(Wv, Dv, DHv, 2);
    transpose_kernel<<<dim3(Dv/32, Dv/32, 1),   dim3(32, 8)>>>(Wo, Dv, Dv, 3);

    qkv_mma_kernel<<<dim3(Mv/128, Hv, 3), 256>>>(x, bq, bk, bv);

    size_t smem = (size_t)25664 * sizeof(float);   // 102,656 B
    cudaFuncSetAttribute(attn_kernel,
                         cudaFuncAttributeMaxDynamicSharedMemorySize, (int)smem);
    attn_kernel<<<dim3(Bv*Hv, Sv/64), 256, smem>>>();

    proj_mma_kernel<<<dim3(Mv/128, Dv/64), 256>>>(bo, out);
}

// round 13
// speedup vs baseline: 2.9195x; 1.7176x over previous
#include <cuda_runtime.h>
#include <cuda_bf16.h>
#include <cstdint>
#include <math.h>

#define Bv 2
#define Sv 2048
#define Dv 1024
#define Hv 16
#define DHv 64
#define Mv (Bv*Sv)        // 4096
#define PADK 36
#define PADQ 68

// Scratch (module-static device globals; no runtime allocation)
__device__ float g_q[(size_t)Bv*Hv*Sv*DHv];   // [b][h][s][dh]
__device__ float g_k[(size_t)Bv*Hv*Sv*DHv];   // [b][h][s][dh]
__device__ float g_vt[(size_t)Bv*Hv*DHv*Sv];  // [b][h][dh][s]  (V transposed)
__device__ float g_o[(size_t)Bv*Sv*Dv];       // [b][s][h*DH+dh]
__device__ float g_wt[(size_t)3*Hv*DHv*Dv];   // W^T per matrix/head: [mtx][h][n][k]
__device__ float g_wot[(size_t)Dv*Dv];        // Wo^T: [n][k]

// ---------------------------------------------------------------------------
// tf32 helpers (mma.sync path — tcgen05 unavailable on this build target)
// ---------------------------------------------------------------------------
__device__ __forceinline__ uint32_t f2tf(float x) {
    uint32_t r;
    asm("cvt.rna.tf32.f32 %0, %1;" : "=r"(r) : "f"(x));
    return r;
}

__device__ __forceinline__ void mma_tf32(float* c, const uint32_t* a, const uint32_t* b) {
    asm volatile(
        "mma.sync.aligned.m16n8k8.row.col.f32.tf32.tf32.f32 "
        "{%0,%1,%2,%3}, {%4,%5,%6,%7}, {%8,%9}, {%0,%1,%2,%3};"
        : "+f"(c[0]), "+f"(c[1]), "+f"(c[2]), "+f"(c[3])
        : "r"(a[0]), "r"(a[1]), "r"(a[2]), "r"(a[3]), "r"(b[0]), "r"(b[1]));
}

// ---------------------------------------------------------------------------
// Weight transpose: dst[b][c][r] = src[b][r][c].
// ---------------------------------------------------------------------------
__global__ __launch_bounds__(256) void transpose_kernel(
    const float* __restrict__ src, int R, int C, int which)
{
    __shared__ float t[32][33];
    float* dstbase = (which < 3) ? (g_wt + (size_t)which * Hv * DHv * Dv) : g_wot;

    const int b  = blockIdx.z;
    const float* s = src + (size_t)b * R * C;
    float* d       = dstbase + (size_t)b * R * C;
    const int r0 = blockIdx.x * 32, c0 = blockIdx.y * 32;
    const int tx = threadIdx.x, ty = threadIdx.y;

    #pragma unroll
    for (int i = 0; i < 4; i++)
        t[ty + 8*i][tx] = s[(size_t)(r0 + ty + 8*i) * C + c0 + tx];
    __syncthreads();
    #pragma unroll
    for (int i = 0; i < 4; i++)
        d[(size_t)(c0 + ty + 8*i) * R + r0 + tx] = t[tx][ty + 8*i];
}

// ---------------------------------------------------------------------------
// mma.sync tf32 GEMM core: acc[128x64] += A[128xDv] @ B[64xDv]^T.
// 256 threads = 8 warps in 4(M) x 2(N); warp tile 32x32 = 2x4 m16n8k8 frags.
// ---------------------------------------------------------------------------
__device__ __forceinline__ void gemm_mma_128x64(
    const float* __restrict__ Arows, const float* __restrict__ Brows,
    float acc[2][4][4], float* As /*[128*PADK]*/, float* Bs /*[64*PADK]*/)
{
    const int tid  = threadIdx.x;
    const int wid  = tid >> 5;
    const int lane = tid & 31;
    const int g    = lane >> 2;
    const int t    = lane & 3;
    const int wm   = (wid & 3) * 32;
    const int wn   = (wid >> 2) * 32;

    for (int kc = 0; kc < Dv; kc += 32) {
        #pragma unroll
        for (int l = 0; l < 4; l++) {
            int fid = tid + l * 256;
            int m   = fid >> 3;
            int kq  = fid & 7;
            float4 v = *(const float4*)&Arows[(size_t)m * Dv + kc + kq * 4];
            uint4 u;
            u.x = f2tf(v.x); u.y = f2tf(v.y); u.z = f2tf(v.z); u.w = f2tf(v.w);
            *(uint4*)&As[m * PADK + kq * 4] = u;
        }
        #pragma unroll
        for (int l = 0; l < 2; l++) {
            int fid = tid + l * 256;
            int n   = fid >> 3;
            int kq  = fid & 7;
            float4 v = *(const float4*)&Brows[(size_t)n * Dv + kc + kq * 4];
            uint4 u;
            u.x = f2tf(v.x); u.y = f2tf(v.y); u.z = f2tf(v.z); u.w = f2tf(v.w);
            *(uint4*)&Bs[n * PADK + kq * 4] = u;
        }
        __syncthreads();

        #pragma unroll
        for (int ks = 0; ks < 32; ks += 8) {
            uint32_t a[2][4], b[4][2];
            #pragma unroll
            for (int mi = 0; mi < 2; mi++) {
                int r0 = wm + mi * 16 + g;
                a[mi][0] = __float_as_uint(As[r0 * PADK + ks + t]);
                a[mi][1] = __float_as_uint(As[(r0 + 8) * PADK + ks + t]);
                a[mi][2] = __float_as_uint(As[r0 * PADK + ks + t + 4]);
                a[mi][3] = __float_as_uint(As[(r0 + 8) * PADK + ks + t + 4]);
            }
            #pragma unroll
            for (int ni = 0; ni < 4; ni++) {
                int nr = wn + ni * 8 + g;
                b[ni][0] = __float_as_uint(Bs[nr * PADK + ks + t]);
                b[ni][1] = __float_as_uint(Bs[nr * PADK + ks + t + 4]);
            }
            #pragma unroll
            for (int mi = 0; mi < 2; mi++)
                #pragma unroll
                for (int ni = 0; ni < 4; ni++)
                    mma_tf32(acc[mi][ni], a[mi], b[ni]);
        }
        __syncthreads();
    }
}

// ---------------------------------------------------------------------------
// Kernel 1: QKV projection via mma.sync tf32.  grid(Mv/128, H, 3), block 256.
// V (mtx==2) is written TRANSPOSED to g_vt[b][h][dh][s] for the PV mma.
// ---------------------------------------------------------------------------
__global__ __launch_bounds__(256) void qkv_mma_kernel(
    const float* __restrict__ x,
    const float* __restrict__ bq,
    const float* __restrict__ bk,
    const float* __restrict__ bv)
{
    __shared__ float As[128 * PADK];
    __shared__ float Bs[64 * PADK];

    const int h   = blockIdx.y;
    const int mtx = blockIdx.z;
    const int r0  = blockIdx.x * 128;

    const float* Brows = g_wt + ((size_t)(mtx * Hv + h) * DHv) * Dv;
    const float* bias  = ((mtx == 0) ? bq : (mtx == 1) ? bk : bv) + h * DHv;

    float acc[2][4][4] = {};
    gemm_mma_128x64(x + (size_t)r0 * Dv, Brows, acc, As, Bs);

    const int lane = threadIdx.x & 31;
    const int wid  = threadIdx.x >> 5;
    const int g    = lane >> 2;
    const int t    = lane & 3;
    const int wm   = (wid & 3) * 32;
    const int wn   = (wid >> 2) * 32;

    if (mtx == 2) {
        // transposed store: g_vt[(b*Hv+h)*DHv + col][s]
        #pragma unroll
        for (int mi = 0; mi < 2; mi++) {
            #pragma unroll
            for (int ni = 0; ni < 4; ni++) {
                int col = wn + ni * 8 + 2 * t;
                #pragma unroll
                for (int half = 0; half < 2; half++) {
                    int m = r0 + wm + mi * 16 + g + half * 8;
                    int b = m >> 11;
                    int s = m & (Sv - 1);
                    float* base = g_vt + ((size_t)(b * Hv + h) * DHv) * Sv;
                    base[(size_t)(col + 0) * Sv + s] = acc[mi][ni][2*half + 0] + bias[col + 0];
                    base[(size_t)(col + 1) * Sv + s] = acc[mi][ni][2*half + 1] + bias[col + 1];
                }
            }
        }
    } else {
        float* out = (mtx == 0) ? g_q : g_k;
        #pragma unroll
        for (int mi = 0; mi < 2; mi++) {
            #pragma unroll
            for (int ni = 0; ni < 4; ni++) {
                int col = wn + ni * 8 + 2 * t;
                #pragma unroll
                for (int half = 0; half < 2; half++) {
                    int m = r0 + wm + mi * 16 + g + half * 8;
                    int b = m >> 11;
                    int s = m & (Sv - 1);
                    float* dst = out + ((size_t)(b * Hv + h) * Sv + s) * DHv + col;
                    float2 w;
                    w.x = acc[mi][ni][2*half + 0] + bias[col + 0];
                    w.y = acc[mi][ni][2*half + 1] + bias[col + 1];
                    *(float2*)dst = w;
                }
            }
        }
    }
}

// ---------------------------------------------------------------------------
// Kernel 3: output projection via mma.sync tf32.  grid(Mv/128, Dv/64), block 256.
// ---------------------------------------------------------------------------
__global__ __launch_bounds__(256) void proj_mma_kernel(
    const float* __restrict__ bo, float* __restrict__ out)
{
    __shared__ float As[128 * PADK];
    __shared__ float Bs[64 * PADK];

    const int r0 = blockIdx.x * 128;
    const int n0 = blockIdx.y * 64;

    float acc[2][4][4] = {};
    gemm_mma_128x64(g_o + (size_t)r0 * Dv, g_wot + (size_t)n0 * Dv, acc, As, Bs);

    const int lane = threadIdx.x & 31;
    const int wid  = threadIdx.x >> 5;
    const int g    = lane >> 2;
    const int t    = lane & 3;
    const int wm   = (wid & 3) * 32;
    const int wn   = (wid >> 2) * 32;

    #pragma unroll
    for (int mi = 0; mi < 2; mi++) {
        #pragma unroll
        for (int ni = 0; ni < 4; ni++) {
            int col = n0 + wn + ni * 8 + 2 * t;
            #pragma unroll
            for (int half = 0; half < 2; half++) {
                int m = r0 + wm + mi * 16 + g + half * 8;
                float* dst = out + (size_t)m * Dv + col;
                float2 w;
                w.x = acc[mi][ni][2*half + 0] + bo[col + 0];
                w.y = acc[mi][ni][2*half + 1] + bo[col + 1];
                *(float2*)dst = w;
            }
        }
    }
}

// ---------------------------------------------------------------------------
// Kernel 2: flash attention, fully tensorized.  grid(B*H, S/64), block 256.
// Warps 0-3: compute (S mma -> register softmax -> PV mma), warp w owns
// score/output rows w*16..w*16+15 end-to-end (corr/l_run in registers).
// Warps 4-7: loaders — copy next K tile (g_k, tf32) and V tile (g_vt,
// [dh][s] tf32) into the alternate smem buffer during compute.
// One __syncthreads per KV tile.
// Smem (floats): Qs@0[64*68] | Ks0@4352 Ks1@8704 | Vt0@13056 Vt1@17408 |
//                Ps@21760[64*68]   total 26112 f = 104448 B (2 CTA/SM)
// ---------------------------------------------------------------------------
__global__ __launch_bounds__(256) void attn_kernel()
{
    extern __shared__ float sm[];
    float* Qs = sm;
    float* Ps = sm + 21760;

    const int bh  = blockIdx.x;                 // b*H + h
    const int s0  = blockIdx.y * 64;
    const int tid = threadIdx.x;
    const int wid = tid >> 5;
    const int lane = tid & 31;
    const int g   = lane >> 2;
    const int t   = lane & 3;
    const int wm  = (wid & 3) * 16;

    const float* qbase  = g_q  + (size_t)bh * Sv * DHv;
    const float* kbase  = g_k  + (size_t)bh * Sv * DHv;
    const float* vtbase = g_vt + (size_t)bh * DHv * Sv;

    // All threads: Q tile -> tf32, pre-scaled by 1/8 (exact)
    #pragma unroll
    for (int l = 0; l < 4; l++) {
        int fid = tid + l * 256;
        int row = fid >> 4, c = fid & 15;
        float4 v = *(const float4*)&qbase[(size_t)(s0 + row) * DHv + c * 4];
        uint4 u;
        u.x = f2tf(v.x * 0.125f); u.y = f2tf(v.y * 0.125f);
        u.z = f2tf(v.z * 0.125f); u.w = f2tf(v.w * 0.125f);
        *(uint4*)&Qs[row * PADQ + c * 4] = u;
    }

    // Loaders fill buffer 0 with tile 0
    if (wid >= 4) {
        const int ltid = tid - 128;
        float* Kd = sm + 4352;
        float* Vd = sm + 13056;
        #pragma unroll
        for (int l = 0; l < 8; l++) {
            int fid = ltid + l * 128;
            int row = fid >> 4, c = fid & 15;
            float4 kv = *(const float4*)&kbase[(size_t)row * DHv + c * 4];
            uint4 uk;
            uk.x = f2tf(kv.x); uk.y = f2tf(kv.y); uk.z = f2tf(kv.z); uk.w = f2tf(kv.w);
            *(uint4*)&Kd[row * PADQ + c * 4] = uk;
            float4 vv = *(const float4*)&vtbase[(size_t)row * Sv + c * 4];
            uint4 uv;
            uv.x = f2tf(vv.x); uv.y = f2tf(vv.y); uv.z = f2tf(vv.z); uv.w = f2tf(vv.w);
            *(uint4*)&Vd[row * PADQ + c * 4] = uv;
        }
    }
    __syncthreads();

    float oacc[8][4] = {};
    float m_run[2] = { -INFINITY, -INFINITY };
    float l_run[2] = { 0.f, 0.f };

    int it = 0;
    for (int t0 = 0; t0 < Sv; t0 += 64, it ^= 1) {
        if (wid >= 4) {
            // Loaders: next tile -> alternate buffer
            if (t0 + 64 < Sv) {
                const int ltid = tid - 128;
                float* Kd = sm + 4352  + (it ^ 1) * 4352;
                float* Vd = sm + 13056 + (it ^ 1) * 4352;
                #pragma unroll
                for (int l = 0; l < 8; l++) {
                    int fid = ltid + l * 128;
                    int row = fid >> 4, c = fid & 15;
                    float4 kv = *(const float4*)&kbase[(size_t)(t0 + 64 + row) * DHv + c * 4];
                    uint4 uk;
                    uk.x = f2tf(kv.x); uk.y = f2tf(kv.y); uk.z = f2tf(kv.z); uk.w = f2tf(kv.w);
                    *(uint4*)&Kd[row * PADQ + c * 4] = uk;
                    float4 vv = *(const float4*)&vtbase[(size_t)row * Sv + t0 + 64 + c * 4];
                    uint4 uv;
                    uv.x = f2tf(vv.x); uv.y = f2tf(vv.y); uv.z = f2tf(vv.z); uv.w = f2tf(vv.w);
                    *(uint4*)&Vd[row * PADQ + c * 4] = uv;
                }
            }
        } else {
            const float* Ks = sm + 4352  + it * 4352;
            const float* Vt = sm + 13056 + it * 4352;

            // S = Q @ K^T : warp-tile m16 x n64
            float sacc[8][4] = {};
            #pragma unroll
            for (int ks = 0; ks < 64; ks += 8) {
                uint32_t a[4];
                a[0] = __float_as_uint(Qs[(wm + g) * PADQ + ks + t]);
                a[1] = __float_as_uint(Qs[(wm + g + 8) * PADQ + ks + t]);
                a[2] = __float_as_uint(Qs[(wm + g) * PADQ + ks + t + 4]);
                a[3] = __float_as_uint(Qs[(wm + g + 8) * PADQ + ks + t + 4]);
                #pragma unroll
                for (int ni = 0; ni < 8; ni++) {
                    uint32_t b[2];
                    b[0] = __float_as_uint(Ks[(ni * 8 + g) * PADQ + ks + t]);
                    b[1] = __float_as_uint(Ks[(ni * 8 + g) * PADQ + ks + t + 4]);
                    mma_tf32(sacc[ni], a, b);
                }
            }

            // Register online softmax; P -> Ps as tf32
            float corr[2];
            #pragma unroll
            for (int half = 0; half < 2; half++) {
                const int r = wm + g + half * 8;
                float mloc = -INFINITY;
                #pragma unroll
                for (int ni = 0; ni < 8; ni++)
                    mloc = fmaxf(mloc, fmaxf(sacc[ni][2*half], sacc[ni][2*half+1]));
                mloc = fmaxf(mloc, __shfl_xor_sync(0xffffffffu, mloc, 1, 4));
                mloc = fmaxf(mloc, __shfl_xor_sync(0xffffffffu, mloc, 2, 4));
                float mnew = fmaxf(m_run[half], mloc);
                corr[half] = __expf(m_run[half] - mnew);
                float sum = 0.f;
                #pragma unroll
                for (int ni = 0; ni < 8; ni++) {
                    float p0 = __expf(sacc[ni][2*half]   - mnew);
                    float p1 = __expf(sacc[ni][2*half+1] - mnew);
                    uint2 up; up.x = f2tf(p0); up.y = f2tf(p1);
                    *(uint2*)&Ps[r * PADQ + ni * 8 + 2 * t] = up;
                    sum += p0 + p1;
                }
                sum += __shfl_xor_sync(0xffffffffu, sum, 1, 4);
                sum += __shfl_xor_sync(0xffffffffu, sum, 2, 4);
                l_run[half] = l_run[half] * corr[half] + sum;
                m_run[half] = mnew;
            }
            __syncwarp();

            // Rescale output accumulators (rows g -> corr[0], g+8 -> corr[1])
            #pragma unroll
            for (int ni = 0; ni < 8; ni++) {
                oacc[ni][0] *= corr[0]; oacc[ni][1] *= corr[0];
                oacc[ni][2] *= corr[1]; oacc[ni][3] *= corr[1];
            }

            // O += P @ V : A from Ps (rows wm..wm+15), B from Vt [dh][kv]
            #pragma unroll
            for (int ks = 0; ks < 64; ks += 8) {
                uint32_t a[4];
                a[0] = __float_as_uint(Ps[(wm + g) * PADQ + ks + t]);
                a[1] = __float_as_uint(Ps[(wm + g + 8) * PADQ + ks + t]);
                a[2] = __float_as_uint(Ps[(wm + g) * PADQ + ks + t + 4]);
                a[3] = __float_as_uint(Ps[(wm + g + 8) * PADQ + ks + t + 4]);
                #pragma unroll
                for (int ni = 0; ni < 8; ni++) {
                    uint32_t b[2];
                    b[0] = __float_as_uint(Vt[(ni * 8 + g) * PADQ + ks + t]);
                    b[1] = __float_as_uint(Vt[(ni * 8 + g) * PADQ + ks + t + 4]);
                    mma_tf32(oacc[ni], a, b);
                }
            }
        }
        __syncthreads();   // buffer swap: compute done reading 'it', loaders done writing 'it^1'
    }

    // Epilogue (compute warps): normalize, write concat layout [b][s][h*DH+dh]
    if (wid < 4) {
        const int b_idx = bh / Hv;
        const int h     = bh % Hv;
        float inv0 = 1.f / l_run[0];
        float inv1 = 1.f / l_run[1];
        #pragma unroll
        for (int half = 0; half < 2; half++) {
            int r = s0 + wm + g + half * 8;
            float inv = half ? inv1 : inv0;
            float* dst = g_o + ((size_t)b_idx * Sv + r) * Dv + h * DHv;
            #pragma unroll
            for (int ni = 0; ni < 8; ni++) {
                float2 w;
                w.x = oacc[ni][2*half + 0] * inv;
                w.y = oacc[ni][2*half + 1] * inv;
                *(float2*)(dst + ni * 8 + 2 * t) = w;
            }
        }
    }
}

// ---------------------------------------------------------------------------
extern "C" void kernel_launch(void* const* d_in, const int* in_sizes, int n_in,
                              void* d_out, int out_size)
{
    const float* x  = (const float*)d_in[0];
    const float* Wq = (const float*)d_in[1];
    const float* bq = (const float*)d_in[2];
    const float* Wk = (const float*)d_in[3];
    const float* bk = (const float*)d_in[4];
    const float* Wv = (const float*)d_in[5];
    const float* bv = (const float*)d_in[6];
    const float* Wo = (const float*)d_in[7];
    const float* bo = (const float*)d_in[8];
    float* out = (float*)d_out;

    // Pre-transpose weights into [n][k] layout for mma B operands
    transpose_kernel<<<dim3(Dv/32, DHv/32, Hv), dim3(32, 8)>>>(Wq, Dv, DHv, 0);
    transpose_kernel<<<dim3(Dv/32, DHv/32, Hv), dim3(32, 8)>>>(Wk, Dv, DHv, 1);
    transpose_kernel<<<dim3(Dv/32, DHv/32, Hv), dim3(32, 8)>>>(Wv, Dv, DHv, 2);
    transpose_kernel<<<dim3(Dv/32, Dv/32, 1),   dim3(32, 8)>>>(Wo, Dv, Dv, 3);

    qkv_mma_kernel<<<dim3(Mv/128, Hv, 3), 256>>>(x, bq, bk, bv);

    size_t smem = (size_t)26112 * sizeof(float);   // 104,448 B
    cudaFuncSetAttribute(attn_kernel,
                         cudaFuncAttributeMaxDynamicSharedMemorySize, (int)smem);
    attn_kernel<<<dim3(Bv*Hv, Sv/64), 256, smem>>>();

    proj_mma_kernel<<<dim3(Mv/128, Dv/64), 256>>>(bo, out);
}